// round 13
// baseline (speedup 1.0000x reference)
#include <cuda_runtime.h>
#include <cuda_fp16.h>

#define Nn 10000
#define Ee 100000
#define Cc 32
#define Gg 64
#define BN_EPS 1e-5f

typedef unsigned long long u64;
typedef unsigned int u32;

// ---- scratch (static device globals; zero-initialized at load) ----
__device__ __align__(16) u64   g_T2[(size_t)Nn * 256];   // 20.48 MB fp16 T
__device__ __align__(16) float g_xb[Nn * Cc];            // x @ b2
__device__ __align__(16) float g_xr[Nn * Cc];            // x @ root + bias
__device__ __align__(16) float g_agg[Nn * Cc];
__device__ float g_deg[Nn];
__device__ __align__(16) float g_pool[Gg * Cc];
__device__ float g_pcnt[Gg];
__device__ unsigned g_done;                              // node2 last-block counter
__device__ unsigned g_done2;                             // k_T1 scan arrival counter
// CSR-by-src (built once per replay, used by both edge passes)
__device__ int g_scnt[Nn];                               // out-degree histogram
__device__ int g_cur[Nn];                                // fill cursor
__device__ int g_rowptr[Nn + 1];
__device__ __align__(16) float4 g_sea[Ee];               // sorted edge_attr
__device__ int g_ssrc[Ee];                               // sorted src
__device__ int g_sdst[Ee];                               // sorted dst

__device__ __forceinline__ void red_add_v4(float* addr, float a, float b, float c, float d) {
    asm volatile("red.global.add.v4.f32 [%0], {%1, %2, %3, %4};"
                 :: "l"(addr), "f"(a), "f"(b), "f"(c), "f"(d) : "memory");
}
__device__ __forceinline__ u32 h2pack(float lo, float hi) {
    __half2 h = __floats2half2_rn(lo, hi);
    return *(u32*)&h;
}
__device__ __forceinline__ void mma16816(float c[4], u32 a0, u32 a1, u32 a2, u32 a3,
                                         u32 b0, u32 b1) {
    asm("mma.sync.aligned.m16n8k16.row.col.f32.f16.f16.f32 "
        "{%0,%1,%2,%3}, {%4,%5,%6,%7}, {%8,%9}, {%0,%1,%2,%3};"
        : "+f"(c[0]), "+f"(c[1]), "+f"(c[2]), "+f"(c[3])
        : "r"(a0), "r"(a1), "r"(a2), "r"(a3), "r"(b0), "r"(b1));
}

// ---- k_T: T = x@w2 (HMMA) + xb = x@b2 (warps 0-3) + xr = x@root + bias (warps 4-7).
// Layer 1 (ei != null): fused deg + src-histogram; last-arriving block does the CSR scan.
// Layer 2 (bg != null): input tile = BN1(agg/deg + xr) ReLU on the fly; resets agg.
__global__ void __launch_bounds__(512, 1)
k_T(const float* __restrict__ xin, const float* __restrict__ w2,
    const float* __restrict__ b2, const float* __restrict__ root,
    const float* __restrict__ bias, const int* __restrict__ ei,
    const float* __restrict__ bg, const float* __restrict__ bb,
    const float* __restrict__ bm, const float* __restrict__ bv) {
    int tid = threadIdx.x;
    int lane = tid & 31;
    int w = tid >> 5;
    int tg = lane & 3;
    int gr = lane >> 2;
    bool l2 = (bg != nullptr);

    if (ei) {   // layer 1: deg (by dst) + out-degree histogram (by src)
        for (int e = blockIdx.x * 512 + tid; e < Ee; e += gridDim.x * 512) {
            atomicAdd(&g_deg[__ldg(&ei[Ee + e])], 1.f);
            atomicAdd(&g_scnt[__ldg(&ei[e])], 1);
        }
        // last-arriving block performs the exclusive scan (others proceed to MMAs)
        __shared__ bool sLast;
        __threadfence();
        __syncthreads();
        if (tid == 0) sLast = (atomicAdd(&g_done2, 1u) == gridDim.x - 1);
        __syncthreads();
        if (sLast) {
            __threadfence();
            const int ITEMS = 20;               // 512*20 >= Nn
            int base = tid * ITEMS;
            int v[ITEMS];
            int sum = 0;
#pragma unroll
            for (int i = 0; i < ITEMS; i++) {
                int c = (base + i < Nn) ? g_scnt[base + i] : 0;
                v[i] = sum; sum += c;
            }
            int s = sum;
#pragma unroll
            for (int d = 1; d < 32; d <<= 1) {
                int u = __shfl_up_sync(0xffffffffu, s, d);
                if (lane >= d) s += u;
            }
            __shared__ int wsum[16];
            if (lane == 31) wsum[w] = s;
            __syncthreads();
            if (w == 0 && lane < 16) {
                int ws = wsum[lane];
#pragma unroll
                for (int d = 1; d < 16; d <<= 1) {
                    int u = __shfl_up_sync(0xffffu, ws, d);
                    if (lane >= d) ws += u;
                }
                wsum[lane] = ws;
            }
            __syncthreads();
            int off = ((w > 0) ? wsum[w - 1] : 0) + (s - sum);
#pragma unroll
            for (int i = 0; i < ITEMS; i++)
                if (base + i < Nn) g_rowptr[base + i] = off + v[i];
            if (tid == 511) g_rowptr[Nn] = off + sum;
            if (tid == 0) g_done2 = 0;
            __threadfence();
        }
    }

    u32 Bf[4][2][2][2];
#pragma unroll
    for (int q = 0; q < 4; q++)
#pragma unroll
        for (int kk = 0; kk < 2; kk++) {
            const float* rb = w2 + (2 * w + kk) * 1024 + q * 8 + gr;
#pragma unroll
            for (int st = 0; st < 2; st++) {
                int i0 = 2 * tg + 16 * st;
                Bf[q][kk][st][0] = h2pack(__ldg(&rb[i0 * 32]),       __ldg(&rb[(i0 + 1) * 32]));
                Bf[q][kk][st][1] = h2pack(__ldg(&rb[(i0 + 8) * 32]), __ldg(&rb[(i0 + 9) * 32]));
            }
        }
    u32 Bs[2][2];
    float2 biasv = make_float2(0.f, 0.f);
    if (w < 8) {
        const float* src = (w < 4) ? (b2 + w * 8 + gr) : (root + (w - 4) * 8 + gr);
#pragma unroll
        for (int st = 0; st < 2; st++) {
            int i0 = 2 * tg + 16 * st;
            Bs[st][0] = h2pack(__ldg(&src[i0 * 32]),       __ldg(&src[(i0 + 1) * 32]));
            Bs[st][1] = h2pack(__ldg(&src[(i0 + 8) * 32]), __ldg(&src[(i0 + 9) * 32]));
        }
        if (w >= 4) biasv = __ldg((const float2*)(bias + (w - 4) * 8 + 2 * tg));
    }

    float scale = 0.f, shift = 0.f;
    if (l2) {
        int i = tid & 31;
        float s = rsqrtf(__ldg(&bv[i]) + BN_EPS) * __ldg(&bg[i]);
        scale = s;
        shift = __ldg(&bb[i]) - __ldg(&bm[i]) * s;
    }

    __shared__ __half xs[16 * 40];
    __shared__ u64 ts[16 * 256];

    int tile = blockIdx.x;
    float pA = 0.f, pX = 0.f;
    if (tile < 625) {
        if (l2) { pA = g_agg[tile * 512 + tid]; pX = g_xr[tile * 512 + tid]; }
        else      pA = __ldg(&xin[tile * 512 + tid]);
    }

    for (; tile < 625; tile += gridDim.x) {
        int nb = tile * 16;
        int j = tid >> 5, i = tid & 31;
        float xv;
        if (l2) {
            float dg = fmaxf(g_deg[nb + j], 1.f);
            xv = fmaxf((pA / dg + pX) * scale + shift, 0.f);
            g_agg[tile * 512 + tid] = 0.f;
        } else xv = pA;
        xs[j * 40 + i] = __float2half(xv);
        __syncthreads();

        const u32* xp = (const u32*)xs;
        int ab = gr * 20 + tg;
        u32 a0 = xp[ab],       a1 = xp[ab + 160];
        u32 a2 = xp[ab + 4],   a3 = xp[ab + 164];
        u32 a4 = xp[ab + 8],   a5 = xp[ab + 168];
        u32 a6 = xp[ab + 12],  a7 = xp[ab + 172];

        int tn = tile + gridDim.x;
        if (tn < 625) {
            if (l2) { pA = g_agg[tn * 512 + tid]; pX = g_xr[tn * 512 + tid]; }
            else      pA = __ldg(&xin[tn * 512 + tid]);
        }

        int x4 = (gr & 3) * 4;
#pragma unroll
        for (int q = 0; q < 4; q++) {
            float c[4] = {0.f, 0.f, 0.f, 0.f};
            float d[4] = {0.f, 0.f, 0.f, 0.f};
            mma16816(c, a0, a1, a2, a3, Bf[q][0][0][0], Bf[q][0][0][1]);
            mma16816(c, a4, a5, a6, a7, Bf[q][0][1][0], Bf[q][0][1][1]);
            mma16816(d, a0, a1, a2, a3, Bf[q][1][0][0], Bf[q][1][0][1]);
            mma16816(d, a4, a5, a6, a7, Bf[q][1][1][0], Bf[q][1][1][1]);
            u64 p0 = ((u64)h2pack(d[0], d[1]) << 32) | h2pack(c[0], c[1]);
            u64 p1 = ((u64)h2pack(d[2], d[3]) << 32) | h2pack(c[2], c[3]);
            int c0 = w * 16 + q * 4 + tg;
            ts[gr * 256       + (c0 ^ x4)] = p0;
            ts[(gr + 8) * 256 + (c0 ^ x4)] = p1;
        }
        if (w < 8) {
            float c[4] = {0.f, 0.f, 0.f, 0.f};
            mma16816(c, a0, a1, a2, a3, Bs[0][0], Bs[0][1]);
            mma16816(c, a4, a5, a6, a7, Bs[1][0], Bs[1][1]);
            if (w < 4) {
                int o = w * 8 + 2 * tg;
                *(float2*)(g_xb + (nb + gr)     * 32 + o) = make_float2(c[0], c[1]);
                *(float2*)(g_xb + (nb + gr + 8) * 32 + o) = make_float2(c[2], c[3]);
            } else {
                int o = (w - 4) * 8 + 2 * tg;
                *(float2*)(g_xr + (nb + gr)     * 32 + o) =
                    make_float2(c[0] + biasv.x, c[1] + biasv.y);
                *(float2*)(g_xr + (nb + gr + 8) * 32 + o) =
                    make_float2(c[2] + biasv.x, c[3] + biasv.y);
            }
        }
        __syncthreads();

        u64* dst = g_T2 + (size_t)nb * 256;
#pragma unroll
        for (int r = 0; r < 8; r++) {
            int i64 = r * 512 + tid;
            int row = i64 >> 8, cc = i64 & 255;
            dst[i64] = ts[row * 256 + (cc ^ ((row & 3) * 4))];
        }
        __syncthreads();
    }
}

// ---- k_fill: scatter edges into src-sorted order (records materialized) ----
__global__ void __launch_bounds__(256)
k_fill(const int* __restrict__ ei, const float* __restrict__ ea) {
    int e = blockIdx.x * blockDim.x + threadIdx.x;
    if (e >= Ee) return;
    int s = __ldg(&ei[e]);
    int pos = g_rowptr[s] + atomicAdd(&g_cur[s], 1);
    g_ssrc[pos] = s;
    g_sdst[pos] = __ldg(&ei[Ee + e]);
    g_sea[pos] = __ldg((const float4*)ea + e);
}

// ---- edge kernel: 4 CSR-ordered edges/warp; sibling warps share src -> L1-resident T ----
__global__ void __launch_bounds__(256)
k_edge(const float* __restrict__ w1, const float* __restrict__ b1) {
    int wrp = (blockIdx.x * blockDim.x + threadIdx.x) >> 5;
    if (wrp >= Ee / 4) return;
    int lane = threadIdx.x & 31;
    int grp = lane >> 3;
    int q = lane & 7;
    int idx = 4 * wrp + grp;
    int src = __ldg(&g_ssrc[idx]);
    int dst = __ldg(&g_sdst[idx]);
    float4 a = __ldg(&g_sea[idx]);

    float4 bv  = __ldg((const float4*)(b1 + 4 * q));
    float4 w0v = __ldg((const float4*)(w1 + 0 * 32 + 4 * q));
    float4 w1v = __ldg((const float4*)(w1 + 1 * 32 + 4 * q));
    float4 w2v = __ldg((const float4*)(w1 + 2 * 32 + 4 * q));
    float4 w3v = __ldg((const float4*)(w1 + 3 * 32 + 4 * q));
    float h0 = fmaxf(bv.x + a.x * w0v.x + a.y * w1v.x + a.z * w2v.x + a.w * w3v.x, 0.f);
    float h1 = fmaxf(bv.y + a.x * w0v.y + a.y * w1v.y + a.z * w2v.y + a.w * w3v.y, 0.f);
    float h2v = fmaxf(bv.z + a.x * w0v.z + a.y * w1v.z + a.z * w2v.z + a.w * w3v.z, 0.f);
    float h3 = fmaxf(bv.w + a.x * w0v.w + a.y * w1v.w + a.z * w2v.w + a.w * w3v.w, 0.f);
    u32 hlo = h2pack(h0, h1);
    u32 hhi = h2pack(h2v, h3);

    float4 xbv = __ldg((const float4*)(g_xb + src * 32 + 4 * q));
    const uint4* Tp = (const uint4*)(g_T2 + (size_t)src * 256) + q;

    float r0 = xbv.x, r1 = xbv.y, r2 = xbv.z, r3 = xbv.w;
    __half2 z = __floats2half2_rn(0.f, 0.f);
    __half2 aA01 = z, aB01 = z, aA23 = z, aB23 = z;
    int base = lane & 24;
#pragma unroll
    for (int kp = 0; kp < 16; kp++) {
        u32 hh = __shfl_sync(0xffffffffu, (kp & 1) ? hhi : hlo, base + (kp >> 1));
        __half2 hph = *(__half2*)&hh;
        __half2 hA = __low2half2(hph);
        __half2 hB = __high2half2(hph);
        uint4 t = __ldg(&Tp[kp * 8]);
        aA01 = __hfma2(hA, *(__half2*)&t.x, aA01);
        aB01 = __hfma2(hB, *(__half2*)&t.y, aB01);
        aA23 = __hfma2(hA, *(__half2*)&t.z, aA23);
        aB23 = __hfma2(hB, *(__half2*)&t.w, aB23);
        if (kp == 7 || kp == 15) {
            float2 fA01 = __half22float2(aA01), fB01 = __half22float2(aB01);
            float2 fA23 = __half22float2(aA23), fB23 = __half22float2(aB23);
            r0 += fA01.x + fB01.x;  r1 += fA01.y + fB01.y;
            r2 += fA23.x + fB23.x;  r3 += fA23.y + fB23.y;
            aA01 = z; aB01 = z; aA23 = z; aB23 = z;
        }
    }
    red_add_v4(&g_agg[dst * 32 + 4 * q], r0, r1, r2, r3);
}

// ---- node L2 + mean-pool + last-block readout; resets agg/deg/pool/pcnt/scnt/cur ----
__global__ void __launch_bounds__(256)
k_node2(const float* __restrict__ bg, const float* __restrict__ bb,
        const float* __restrict__ bm, const float* __restrict__ bv,
        const int* __restrict__ batch,
        const float* __restrict__ r1w, const float* __restrict__ r1b,
        const float* __restrict__ r2w, const float* __restrict__ r2b,
        float* __restrict__ out) {
    int t = blockIdx.x * blockDim.x + threadIdx.x;
    if (t < Nn * 8) {
        int n = t >> 3, q = t & 7;
        float4 ag = *(const float4*)(g_agg + n * 32 + 4 * q);
        float4 xr = *(const float4*)(g_xr + n * 32 + 4 * q);
        float inv = 1.f / fmaxf(g_deg[n], 1.f);
        *(float4*)(g_agg + n * 32 + 4 * q) = make_float4(0.f, 0.f, 0.f, 0.f);
        __syncwarp();
        if (q == 0) { g_deg[n] = 0.f; g_scnt[n] = 0; g_cur[n] = 0; }
        float4 g = __ldg((const float4*)(bg + 4 * q));
        float4 b = __ldg((const float4*)(bb + 4 * q));
        float4 m = __ldg((const float4*)(bm + 4 * q));
        float4 v = __ldg((const float4*)(bv + 4 * q));
        float rx = fmaxf((ag.x * inv + xr.x - m.x) * rsqrtf(v.x + BN_EPS) * g.x + b.x, 0.f);
        float ry = fmaxf((ag.y * inv + xr.y - m.y) * rsqrtf(v.y + BN_EPS) * g.y + b.y, 0.f);
        float rz = fmaxf((ag.z * inv + xr.z - m.z) * rsqrtf(v.z + BN_EPS) * g.z + b.z, 0.f);
        float rw = fmaxf((ag.w * inv + xr.w - m.w) * rsqrtf(v.w + BN_EPS) * g.w + b.w, 0.f);
        int gph = __ldg(&batch[n]);
        red_add_v4(&g_pool[gph * 32 + 4 * q], rx, ry, rz, rw);
        if (q == 0) atomicAdd(&g_pcnt[gph], 1.f);
    }

    __shared__ bool isLast;
    __threadfence();
    __syncthreads();
    if (threadIdx.x == 0)
        isLast = (atomicAdd(&g_done, 1u) == gridDim.x - 1);
    __syncthreads();
    if (isLast) {
        __threadfence();
        int gph = threadIdx.x;
        if (gph < Gg) {
            float c = fmaxf(g_pcnt[gph], 1.f);
            float p[Cc];
#pragma unroll
            for (int o = 0; o < Cc; o++) p[o] = g_pool[gph * Cc + o] / c;
            float res = r2b[0];
#pragma unroll
            for (int jj = 0; jj < 16; jj++) {
                float hid = r1b[jj];
#pragma unroll
                for (int o = 0; o < Cc; o++) hid += p[o] * r1w[o * 16 + jj];
                res += fmaxf(hid, 0.f) * r2w[jj];
            }
            out[gph] = res;
#pragma unroll
            for (int o = 0; o < Cc; o++) g_pool[gph * Cc + o] = 0.f;
            g_pcnt[gph] = 0.f;
        }
        if (threadIdx.x == 0) g_done = 0;
    }
}

extern "C" void kernel_launch(void* const* d_in, const int* in_sizes, int n_in,
                              void* d_out, int out_size) {
    const float* x     = (const float*)d_in[0];
    const float* ea    = (const float*)d_in[1];
    const float* e1w1  = (const float*)d_in[2];
    const float* e1b1  = (const float*)d_in[3];
    const float* e1w2  = (const float*)d_in[4];
    const float* e1b2  = (const float*)d_in[5];
    const float* root1 = (const float*)d_in[6];
    const float* bias1 = (const float*)d_in[7];
    const float* e2w1  = (const float*)d_in[8];
    const float* e2b1  = (const float*)d_in[9];
    const float* e2w2  = (const float*)d_in[10];
    const float* e2b2  = (const float*)d_in[11];
    const float* root2 = (const float*)d_in[12];
    const float* bias2 = (const float*)d_in[13];
    const float* bn1g  = (const float*)d_in[14];
    const float* bn1b  = (const float*)d_in[15];
    const float* bn1m  = (const float*)d_in[16];
    const float* bn1v  = (const float*)d_in[17];
    const float* bn2g  = (const float*)d_in[18];
    const float* bn2b  = (const float*)d_in[19];
    const float* bn2m  = (const float*)d_in[20];
    const float* bn2v  = (const float*)d_in[21];
    const float* r1w   = (const float*)d_in[22];
    const float* r1b   = (const float*)d_in[23];
    const float* r2w   = (const float*)d_in[24];
    const float* r2b   = (const float*)d_in[25];
    const int*   eidx  = (const int*)d_in[26];
    const int*   batch = (const int*)d_in[27];
    float* out = (float*)d_out;

    const int THR = 256;
    const int gE  = (Ee + THR - 1) / THR;             // 391 blocks
    const int gEW = (Ee / 4 * 32 + THR - 1) / THR;    // 3125 blocks
    const int gN8 = (Nn * 8 + THR - 1) / THR;         // 313 blocks

    // layer 1: T/xb/xr + deg/scnt histograms + CSR scan (in-kernel)
    k_T<<<148, 512>>>(x, e1w2, e1b2, root1, bias1, eidx,
                      nullptr, nullptr, nullptr, nullptr);
    k_fill<<<gE, THR>>>(eidx, ea);
    k_edge<<<gEW, THR>>>(e1w1, e1b1);

    // layer 2
    k_T<<<148, 512>>>(nullptr, e2w2, e2b2, root2, bias2, nullptr,
                      bn1g, bn1b, bn1m, bn1v);
    k_edge<<<gEW, THR>>>(e2w1, e2b1);

    // node-2 + pool + fused readout + state resets
    k_node2<<<gN8, THR>>>(bn2g, bn2b, bn2m, bn2v, batch,
                          r1w, r1b, r2w, r2b, out);
}

// round 14
// speedup vs baseline: 1.1205x; 1.1205x over previous
#include <cuda_runtime.h>
#include <cuda_fp16.h>

#define Nn 10000
#define Ee 100000
#define Cc 32
#define Gg 64
#define BN_EPS 1e-5f

typedef unsigned long long u64;
typedef unsigned int u32;

// ---- scratch (static device globals; zero-initialized at load) ----
// T2[n][kp][op] u64 = {h2(T[2kp][2op],T[2kp][2op+1]), h2(T[2kp+1][2op],T[2kp+1][2op+1])}
__device__ __align__(16) u64   g_T2[(size_t)Nn * 256];   // 20.48 MB
__device__ __align__(16) float g_xb[Nn * Cc];            // x @ b2
__device__ __align__(16) float g_xr[Nn * Cc];            // x @ root + bias
__device__ __align__(16) float g_agg[Nn * Cc];
__device__ float g_deg[Nn];
__device__ __align__(16) float g_pool[Gg * Cc];
__device__ float g_pcnt[Gg];
__device__ unsigned g_done;                              // last-block arrival counter

__device__ __forceinline__ void red_add_v4(float* addr, float a, float b, float c, float d) {
    asm volatile("red.global.add.v4.f32 [%0], {%1, %2, %3, %4};"
                 :: "l"(addr), "f"(a), "f"(b), "f"(c), "f"(d) : "memory");
}
__device__ __forceinline__ u32 h2pack(float lo, float hi) {
    __half2 h = __floats2half2_rn(lo, hi);
    return *(u32*)&h;
}
__device__ __forceinline__ void mma16816(float c[4], u32 a0, u32 a1, u32 a2, u32 a3,
                                         u32 b0, u32 b1) {
    asm("mma.sync.aligned.m16n8k16.row.col.f32.f16.f16.f32 "
        "{%0,%1,%2,%3}, {%4,%5,%6,%7}, {%8,%9}, {%0,%1,%2,%3};"
        : "+f"(c[0]), "+f"(c[1]), "+f"(c[2]), "+f"(c[3])
        : "r"(a0), "r"(a1), "r"(a2), "r"(a3), "r"(b0), "r"(b1));
}

// ---- k_T: T = x@w2 (HMMA) + xb = x@b2 (warps 0-3) + xr = x@root + bias (warps 4-7).
// Layer 1 (bg==null): input = xin, fused in-degree histogram (ei != null).
// Layer 2 (bg!=null): input tile computed on the fly = BN1(agg/deg + xr) ReLU; resets agg.
__global__ void __launch_bounds__(512, 1)
k_T(const float* __restrict__ xin, const float* __restrict__ w2,
    const float* __restrict__ b2, const float* __restrict__ root,
    const float* __restrict__ bias, const int* __restrict__ ei,
    const float* __restrict__ bg, const float* __restrict__ bb,
    const float* __restrict__ bm, const float* __restrict__ bv) {
    int tid = threadIdx.x;
    int lane = tid & 31;
    int w = tid >> 5;                  // = kp
    int tg = lane & 3;
    int gr = lane >> 2;
    bool l2 = (bg != nullptr);

    if (ei) {   // fused in-degree (layer 1 only)
        for (int e = blockIdx.x * 512 + tid; e < Ee; e += gridDim.x * 512)
            atomicAdd(&g_deg[__ldg(&ei[Ee + e])], 1.f);
    }

    u32 Bf[4][2][2][2];
#pragma unroll
    for (int q = 0; q < 4; q++)
#pragma unroll
        for (int kk = 0; kk < 2; kk++) {
            const float* rb = w2 + (2 * w + kk) * 1024 + q * 8 + gr;
#pragma unroll
            for (int st = 0; st < 2; st++) {
                int i0 = 2 * tg + 16 * st;
                Bf[q][kk][st][0] = h2pack(__ldg(&rb[i0 * 32]),       __ldg(&rb[(i0 + 1) * 32]));
                Bf[q][kk][st][1] = h2pack(__ldg(&rb[(i0 + 8) * 32]), __ldg(&rb[(i0 + 9) * 32]));
            }
        }
    u32 Bs[2][2];
    float2 biasv = make_float2(0.f, 0.f);
    if (w < 8) {
        const float* src = (w < 4) ? (b2 + w * 8 + gr) : (root + (w - 4) * 8 + gr);
#pragma unroll
        for (int st = 0; st < 2; st++) {
            int i0 = 2 * tg + 16 * st;
            Bs[st][0] = h2pack(__ldg(&src[i0 * 32]),       __ldg(&src[(i0 + 1) * 32]));
            Bs[st][1] = h2pack(__ldg(&src[(i0 + 8) * 32]), __ldg(&src[(i0 + 9) * 32]));
        }
        if (w >= 4) biasv = __ldg((const float2*)(bias + (w - 4) * 8 + 2 * tg));
    }

    float scale = 0.f, shift = 0.f;
    if (l2) {
        int i = tid & 31;
        float s = rsqrtf(__ldg(&bv[i]) + BN_EPS) * __ldg(&bg[i]);
        scale = s;
        shift = __ldg(&bb[i]) - __ldg(&bm[i]) * s;
    }

    __shared__ __half xs[16 * 40];
    __shared__ u64 ts[16 * 256];

    int tile = blockIdx.x;
    float pA = 0.f, pX = 0.f;
    if (tile < 625) {
        if (l2) { pA = g_agg[tile * 512 + tid]; pX = g_xr[tile * 512 + tid]; }
        else      pA = __ldg(&xin[tile * 512 + tid]);
    }

    for (; tile < 625; tile += gridDim.x) {
        int nb = tile * 16;
        int j = tid >> 5, i = tid & 31;
        float xv;
        if (l2) {
            float dg = fmaxf(g_deg[nb + j], 1.f);
            xv = fmaxf((pA / dg + pX) * scale + shift, 0.f);
            g_agg[tile * 512 + tid] = 0.f;
        } else xv = pA;
        xs[j * 40 + i] = __float2half(xv);
        __syncthreads();

        const u32* xp = (const u32*)xs;
        int ab = gr * 20 + tg;
        u32 a0 = xp[ab],       a1 = xp[ab + 160];
        u32 a2 = xp[ab + 4],   a3 = xp[ab + 164];
        u32 a4 = xp[ab + 8],   a5 = xp[ab + 168];
        u32 a6 = xp[ab + 12],  a7 = xp[ab + 172];

        int tn = tile + gridDim.x;
        if (tn < 625) {
            if (l2) { pA = g_agg[tn * 512 + tid]; pX = g_xr[tn * 512 + tid]; }
            else      pA = __ldg(&xin[tn * 512 + tid]);
        }

        int x4 = (gr & 3) * 4;
#pragma unroll
        for (int q = 0; q < 4; q++) {
            float c[4] = {0.f, 0.f, 0.f, 0.f};
            float d[4] = {0.f, 0.f, 0.f, 0.f};
            mma16816(c, a0, a1, a2, a3, Bf[q][0][0][0], Bf[q][0][0][1]);
            mma16816(c, a4, a5, a6, a7, Bf[q][0][1][0], Bf[q][0][1][1]);
            mma16816(d, a0, a1, a2, a3, Bf[q][1][0][0], Bf[q][1][0][1]);
            mma16816(d, a4, a5, a6, a7, Bf[q][1][1][0], Bf[q][1][1][1]);
            u64 p0 = ((u64)h2pack(d[0], d[1]) << 32) | h2pack(c[0], c[1]);
            u64 p1 = ((u64)h2pack(d[2], d[3]) << 32) | h2pack(c[2], c[3]);
            int c0 = w * 16 + q * 4 + tg;
            ts[gr * 256       + (c0 ^ x4)] = p0;
            ts[(gr + 8) * 256 + (c0 ^ x4)] = p1;
        }
        if (w < 8) {
            float c[4] = {0.f, 0.f, 0.f, 0.f};
            mma16816(c, a0, a1, a2, a3, Bs[0][0], Bs[0][1]);
            mma16816(c, a4, a5, a6, a7, Bs[1][0], Bs[1][1]);
            if (w < 4) {
                int o = w * 8 + 2 * tg;
                *(float2*)(g_xb + (nb + gr)     * 32 + o) = make_float2(c[0], c[1]);
                *(float2*)(g_xb + (nb + gr + 8) * 32 + o) = make_float2(c[2], c[3]);
            } else {
                int o = (w - 4) * 8 + 2 * tg;
                *(float2*)(g_xr + (nb + gr)     * 32 + o) =
                    make_float2(c[0] + biasv.x, c[1] + biasv.y);
                *(float2*)(g_xr + (nb + gr + 8) * 32 + o) =
                    make_float2(c[2] + biasv.x, c[3] + biasv.y);
            }
        }
        __syncthreads();

        u64* dst = g_T2 + (size_t)nb * 256;
#pragma unroll
        for (int r = 0; r < 8; r++) {
            int i64 = r * 512 + tid;
            int row = i64 >> 8, cc = i64 & 255;
            dst[i64] = ts[row * 256 + (cc ^ ((row & 3) * 4))];
        }
        __syncthreads();
    }
}

// ---- edge kernel: 4 edges/warp, lane = o-quad; ALL 16 T loads hoisted (MLP=16),
//      HFMA2 core with fp32 flush every 8 k-pairs ----
__global__ void __launch_bounds__(256)
k_edge(const float* __restrict__ ea, const int* __restrict__ ei,
       const float* __restrict__ w1, const float* __restrict__ b1) {
    int wrp = (blockIdx.x * blockDim.x + threadIdx.x) >> 5;
    if (wrp >= Ee / 4) return;
    int lane = threadIdx.x & 31;
    int grp = lane >> 3;
    int q = lane & 7;
    int e = 4 * wrp + grp;
    int src = __ldg(&ei[e]);
    int dst = __ldg(&ei[Ee + e]);

    // hoist ALL T loads first: 16 independent LDG.128 in flight
    const uint4* Tp = (const uint4*)(g_T2 + (size_t)src * 256) + q;
    uint4 tv[16];
#pragma unroll
    for (int kp = 0; kp < 16; kp++) tv[kp] = __ldg(&Tp[kp * 8]);
    float4 xbv = __ldg((const float4*)(g_xb + src * 32 + 4 * q));

    float4 a = __ldg((const float4*)ea + e);
    float4 bv  = __ldg((const float4*)(b1 + 4 * q));
    float4 w0v = __ldg((const float4*)(w1 + 0 * 32 + 4 * q));
    float4 w1v = __ldg((const float4*)(w1 + 1 * 32 + 4 * q));
    float4 w2v = __ldg((const float4*)(w1 + 2 * 32 + 4 * q));
    float4 w3v = __ldg((const float4*)(w1 + 3 * 32 + 4 * q));
    float h0 = fmaxf(bv.x + a.x * w0v.x + a.y * w1v.x + a.z * w2v.x + a.w * w3v.x, 0.f);
    float h1 = fmaxf(bv.y + a.x * w0v.y + a.y * w1v.y + a.z * w2v.y + a.w * w3v.y, 0.f);
    float h2v = fmaxf(bv.z + a.x * w0v.z + a.y * w1v.z + a.z * w2v.z + a.w * w3v.z, 0.f);
    float h3 = fmaxf(bv.w + a.x * w0v.w + a.y * w1v.w + a.z * w2v.w + a.w * w3v.w, 0.f);
    u32 hlo = h2pack(h0, h1);          // h[4q], h[4q+1]
    u32 hhi = h2pack(h2v, h3);         // h[4q+2], h[4q+3]

    float r0 = xbv.x, r1 = xbv.y, r2 = xbv.z, r3 = xbv.w;
    __half2 z = __floats2half2_rn(0.f, 0.f);
    __half2 aA01 = z, aB01 = z, aA23 = z, aB23 = z;
    int base = lane & 24;
#pragma unroll
    for (int kp = 0; kp < 16; kp++) {
        u32 hh = __shfl_sync(0xffffffffu, (kp & 1) ? hhi : hlo, base + (kp >> 1));
        __half2 hph = *(__half2*)&hh;           // (h[2kp], h[2kp+1])
        __half2 hA = __low2half2(hph);
        __half2 hB = __high2half2(hph);
        aA01 = __hfma2(hA, *(__half2*)&tv[kp].x, aA01);
        aB01 = __hfma2(hB, *(__half2*)&tv[kp].y, aB01);
        aA23 = __hfma2(hA, *(__half2*)&tv[kp].z, aA23);
        aB23 = __hfma2(hB, *(__half2*)&tv[kp].w, aB23);
        if (kp == 7 || kp == 15) {              // flush to fp32 (chains <= 8 adds)
            float2 fA01 = __half22float2(aA01), fB01 = __half22float2(aB01);
            float2 fA23 = __half22float2(aA23), fB23 = __half22float2(aB23);
            r0 += fA01.x + fB01.x;  r1 += fA01.y + fB01.y;
            r2 += fA23.x + fB23.x;  r3 += fA23.y + fB23.y;
            aA01 = z; aB01 = z; aA23 = z; aB23 = z;
        }
    }
    red_add_v4(&g_agg[dst * 32 + 4 * q], r0, r1, r2, r3);
}

// ---- node L2 + mean-pool scatter + LAST-BLOCK fused readout; resets agg/deg/pool/pcnt ----
__global__ void __launch_bounds__(256)
k_node2(const float* __restrict__ bg, const float* __restrict__ bb,
        const float* __restrict__ bm, const float* __restrict__ bv,
        const int* __restrict__ batch,
        const float* __restrict__ r1w, const float* __restrict__ r1b,
        const float* __restrict__ r2w, const float* __restrict__ r2b,
        float* __restrict__ out) {
    int t = blockIdx.x * blockDim.x + threadIdx.x;
    if (t < Nn * 8) {
        int n = t >> 3, q = t & 7;
        float4 ag = *(const float4*)(g_agg + n * 32 + 4 * q);
        float4 xr = *(const float4*)(g_xr + n * 32 + 4 * q);
        float inv = 1.f / fmaxf(g_deg[n], 1.f);
        *(float4*)(g_agg + n * 32 + 4 * q) = make_float4(0.f, 0.f, 0.f, 0.f);
        __syncwarp();
        if (q == 0) g_deg[n] = 0.f;
        float4 g = __ldg((const float4*)(bg + 4 * q));
        float4 b = __ldg((const float4*)(bb + 4 * q));
        float4 m = __ldg((const float4*)(bm + 4 * q));
        float4 v = __ldg((const float4*)(bv + 4 * q));
        float rx = fmaxf((ag.x * inv + xr.x - m.x) * rsqrtf(v.x + BN_EPS) * g.x + b.x, 0.f);
        float ry = fmaxf((ag.y * inv + xr.y - m.y) * rsqrtf(v.y + BN_EPS) * g.y + b.y, 0.f);
        float rz = fmaxf((ag.z * inv + xr.z - m.z) * rsqrtf(v.z + BN_EPS) * g.z + b.z, 0.f);
        float rw = fmaxf((ag.w * inv + xr.w - m.w) * rsqrtf(v.w + BN_EPS) * g.w + b.w, 0.f);
        int gph = __ldg(&batch[n]);
        red_add_v4(&g_pool[gph * 32 + 4 * q], rx, ry, rz, rw);
        if (q == 0) atomicAdd(&g_pcnt[gph], 1.f);
    }

    __shared__ bool isLast;
    __threadfence();
    __syncthreads();
    if (threadIdx.x == 0)
        isLast = (atomicAdd(&g_done, 1u) == gridDim.x - 1);
    __syncthreads();
    if (isLast) {
        __threadfence();
        int gph = threadIdx.x;
        if (gph < Gg) {
            float c = fmaxf(g_pcnt[gph], 1.f);
            float p[Cc];
#pragma unroll
            for (int o = 0; o < Cc; o++) p[o] = g_pool[gph * Cc + o] / c;
            float res = r2b[0];
#pragma unroll
            for (int jj = 0; jj < 16; jj++) {
                float hid = r1b[jj];
#pragma unroll
                for (int o = 0; o < Cc; o++) hid += p[o] * r1w[o * 16 + jj];
                res += fmaxf(hid, 0.f) * r2w[jj];
            }
            out[gph] = res;
#pragma unroll
            for (int o = 0; o < Cc; o++) g_pool[gph * Cc + o] = 0.f;
            g_pcnt[gph] = 0.f;
        }
        if (threadIdx.x == 0) g_done = 0;
    }
}

extern "C" void kernel_launch(void* const* d_in, const int* in_sizes, int n_in,
                              void* d_out, int out_size) {
    const float* x     = (const float*)d_in[0];
    const float* ea    = (const float*)d_in[1];
    const float* e1w1  = (const float*)d_in[2];
    const float* e1b1  = (const float*)d_in[3];
    const float* e1w2  = (const float*)d_in[4];
    const float* e1b2  = (const float*)d_in[5];
    const float* root1 = (const float*)d_in[6];
    const float* bias1 = (const float*)d_in[7];
    const float* e2w1  = (const float*)d_in[8];
    const float* e2b1  = (const float*)d_in[9];
    const float* e2w2  = (const float*)d_in[10];
    const float* e2b2  = (const float*)d_in[11];
    const float* root2 = (const float*)d_in[12];
    const float* bias2 = (const float*)d_in[13];
    const float* bn1g  = (const float*)d_in[14];
    const float* bn1b  = (const float*)d_in[15];
    const float* bn1m  = (const float*)d_in[16];
    const float* bn1v  = (const float*)d_in[17];
    const float* bn2g  = (const float*)d_in[18];
    const float* bn2b  = (const float*)d_in[19];
    const float* bn2m  = (const float*)d_in[20];
    const float* bn2v  = (const float*)d_in[21];
    const float* r1w   = (const float*)d_in[22];
    const float* r1b   = (const float*)d_in[23];
    const float* r2w   = (const float*)d_in[24];
    const float* r2b   = (const float*)d_in[25];
    const int*   eidx  = (const int*)d_in[26];
    const int*   batch = (const int*)d_in[27];
    float* out = (float*)d_out;

    const int THR = 256;
    const int gEW = (Ee / 4 * 32 + THR - 1) / THR;    // 3125 blocks
    const int gN8 = (Nn * 8 + THR - 1) / THR;         // 313 blocks

    // layer 1
    k_T<<<148, 512>>>(x, e1w2, e1b2, root1, bias1, eidx,
                      nullptr, nullptr, nullptr, nullptr);
    k_edge<<<gEW, THR>>>(ea, eidx, e1w1, e1b1);

    // layer 2 (k_T consumes agg/xr directly; node-1 epilogue fused)
    k_T<<<148, 512>>>(nullptr, e2w2, e2b2, root2, bias2, nullptr,
                      bn1g, bn1b, bn1m, bn1v);
    k_edge<<<gEW, THR>>>(ea, eidx, e2w1, e2b1);

    // node-2 + pool + fused readout (last block)
    k_node2<<<gN8, THR>>>(bn2g, bn2b, bn2m, bn2v, batch,
                          r1w, r1b, r2w, r2b, out);
}